// round 2
// baseline (speedup 1.0000x reference)
#include <cuda_runtime.h>
#include <cuda_bf16.h>

#define NN    50000
#define DIN   128
#define HH    64
#define CC    2
#define EMAX  800000

// ---------------- scratch (static __device__, no allocation) ----------------
__device__ int   d_flag64;
__device__ __align__(16) int   d_edges[2 * EMAX];        // [0..E) src, [E..2E) dst
__device__ __align__(16) float d_deg [NN];
__device__ __align__(16) float d_dinv[NN];
__device__ __align__(16) float d_g1  [(size_t)NN * HH];  // (x@W1)*dinv
__device__ __align__(16) float d_acc1[(size_t)NN * HH];  // aggregate accumulator, layer 1
__device__ __align__(16) float d_g2  [NN * CC];
__device__ __align__(16) float d_acc2[NN * CC];

// ---------------- dtype detection: int64 vs int32 edge_index ----------------
__global__ void k_detect(const int* __restrict__ p) {
    __shared__ int ok;
    if (threadIdx.x == 0) ok = 1;
    __syncthreads();
    int bad = 0;
    for (int i = threadIdx.x; i < 1024; i += blockDim.x) {
        int lo = p[2 * i], hi = p[2 * i + 1];
        if (hi != 0 || lo < 0 || lo >= NN) bad = 1;
    }
    if (bad) atomicAnd(&ok, 0);
    __syncthreads();
    if (threadIdx.x == 0) d_flag64 = ok;
}

__global__ void k_deg_init() {
    int i = blockIdx.x * blockDim.x + threadIdx.x;
    if (i < NN) d_deg[i] = 1.0f;   // self-loop contributes 1
}

// convert edge indices to int32 AND count in-degree (dst half) in one pass
__global__ void k_convert(const void* __restrict__ p, int n2, int E) {
    int i = blockIdx.x * blockDim.x + threadIdx.x;
    if (i >= n2) return;
    int v;
    if (d_flag64) v = (int)((const long long*)p)[i];
    else          v = ((const int*)p)[i];
    d_edges[i] = v;
    if (i >= E) atomicAdd(&d_deg[v], 1.0f);
}

__global__ void k_dinv() {
    int i = blockIdx.x * blockDim.x + threadIdx.x;
    if (i < NN) d_dinv[i] = rsqrtf(d_deg[i]);  // deg >= 1 always
}

// ---------------- layer 1 GEMM: g1 = (x @ W1) * dinv ; acc1 = g1 ------------
// block: 256 threads, 32 nodes/block, each thread -> 1 node x 8 outputs
__global__ void k_gemm1(const float* __restrict__ x, const float* __restrict__ W1) {
    __shared__ float Ws[DIN * HH];       // 32 KB
    __shared__ float xs[32][DIN];        // 16 KB
    const int tid = threadIdx.x;
    const int nb  = blockIdx.x * 32;

    // stage W1 (2048 float4)
    const float4* W4  = (const float4*)W1;
    float4*       Ws4 = (float4*)Ws;
    #pragma unroll
    for (int i = tid; i < (DIN * HH) / 4; i += 256) Ws4[i] = W4[i];

    // stage x tile (32 rows x 128) = 1024 float4
    const float4* x4  = (const float4*)(x + (size_t)nb * DIN);
    float4*       xs4 = (float4*)xs;
    int nvalid = (NN - nb < 32 ? NN - nb : 32) * (DIN / 4);
    for (int i = tid; i < 32 * (DIN / 4); i += 256)
        if (i < nvalid) xs4[i] = x4[i];
    __syncthreads();

    const int n = tid >> 3;          // 0..31  node within tile
    const int o = (tid & 7) * 8;     // 0,8,...,56 output group
    const int node = nb + n;
    if (node >= NN) return;

    float acc[8];
    #pragma unroll
    for (int j = 0; j < 8; j++) acc[j] = 0.0f;

    #pragma unroll 16
    for (int k = 0; k < DIN; k++) {
        const float xv = xs[n][k];
        const float* wr = Ws + k * HH + o;
        #pragma unroll
        for (int j = 0; j < 8; j++) acc[j] = fmaf(xv, wr[j], acc[j]);
    }

    const float di = d_dinv[node];
    float4 v0 = make_float4(acc[0]*di, acc[1]*di, acc[2]*di, acc[3]*di);
    float4 v1 = make_float4(acc[4]*di, acc[5]*di, acc[6]*di, acc[7]*di);
    float4* gp = (float4*)(d_g1   + (size_t)node * HH + o);
    float4* ap = (float4*)(d_acc1 + (size_t)node * HH + o);
    gp[0] = v0; gp[1] = v1;
    ap[0] = v0; ap[1] = v1;   // self-loop init
}

// ---------------- layer 1 scatter: acc1[dst] += g1[src] ---------------------
// one thread per (edge, float4-chunk): E * 16 threads
__global__ void k_scatter1(int E) {
    int t = blockIdx.x * blockDim.x + threadIdx.x;
    int e = t >> 4;
    if (e >= E) return;
    int c = (t & 15) << 2;             // float offset 0..60
    int s = d_edges[e];
    int d = d_edges[E + e];
    const float4 v = *(const float4*)(d_g1 + (size_t)s * HH + c);
    float* dst = d_acc1 + (size_t)d * HH + c;
    asm volatile("red.global.add.v4.f32 [%0], {%1,%2,%3,%4};"
                 :: "l"(dst), "f"(v.x), "f"(v.y), "f"(v.z), "f"(v.w) : "memory");
}

// ---------------- layer 2 GEMM (fused relu+bias on input) -------------------
// out1[i][j] = relu(dinv[i]*acc1[i][j] + b1[j]);  h2 = out1 @ W2;  g2 = h2*dinv
__global__ void k_gemm2(const float* __restrict__ b1, const float* __restrict__ W2) {
    __shared__ float Ws[HH * CC];
    __shared__ float bs[HH];
    if (threadIdx.x < HH * CC) Ws[threadIdx.x] = W2[threadIdx.x];
    if (threadIdx.x < HH)      bs[threadIdx.x] = b1[threadIdx.x];
    __syncthreads();

    int i = blockIdx.x * blockDim.x + threadIdx.x;
    if (i >= NN) return;
    const float di = d_dinv[i];
    const float4* row = (const float4*)(d_acc1 + (size_t)i * HH);
    float a0 = 0.0f, a1 = 0.0f;
    #pragma unroll
    for (int j4 = 0; j4 < HH / 4; j4++) {
        float4 v = row[j4];
        int j = j4 * 4;
        float h;
        h = fmaxf(fmaf(di, v.x, bs[j+0]), 0.0f); a0 = fmaf(h, Ws[(j+0)*2], a0); a1 = fmaf(h, Ws[(j+0)*2+1], a1);
        h = fmaxf(fmaf(di, v.y, bs[j+1]), 0.0f); a0 = fmaf(h, Ws[(j+1)*2], a0); a1 = fmaf(h, Ws[(j+1)*2+1], a1);
        h = fmaxf(fmaf(di, v.z, bs[j+2]), 0.0f); a0 = fmaf(h, Ws[(j+2)*2], a0); a1 = fmaf(h, Ws[(j+2)*2+1], a1);
        h = fmaxf(fmaf(di, v.w, bs[j+3]), 0.0f); a0 = fmaf(h, Ws[(j+3)*2], a0); a1 = fmaf(h, Ws[(j+3)*2+1], a1);
    }
    float2 g = make_float2(a0 * di, a1 * di);
    *(float2*)(d_g2   + i * CC) = g;
    *(float2*)(d_acc2 + i * CC) = g;   // self-loop init
}

// ---------------- layer 2 scatter: one thread per edge ----------------------
__global__ void k_scatter2(int E) {
    int e = blockIdx.x * blockDim.x + threadIdx.x;
    if (e >= E) return;
    int s = d_edges[e];
    int d = d_edges[E + e];
    const float2 v = *(const float2*)(d_g2 + s * CC);
    float* dst = d_acc2 + d * CC;
    asm volatile("red.global.add.v2.f32 [%0], {%1,%2};"
                 :: "l"(dst), "f"(v.x), "f"(v.y) : "memory");
}

// ---------------- final: out = dinv * acc2 + b2 -----------------------------
__global__ void k_final(float* __restrict__ out, const float* __restrict__ b2) {
    int i = blockIdx.x * blockDim.x + threadIdx.x;
    if (i >= NN) return;
    const float di = d_dinv[i];
    float2 a = *(const float2*)(d_acc2 + i * CC);
    float2 o = make_float2(fmaf(di, a.x, b2[0]), fmaf(di, a.y, b2[1]));
    *(float2*)(out + i * CC) = o;
}

// ---------------- launch ----------------------------------------------------
extern "C" void kernel_launch(void* const* d_in, const int* in_sizes, int n_in,
                              void* d_out, int out_size) {
    const float* x  = (const float*)d_in[0];
    const void*  ei = d_in[1];
    const float* W1 = (const float*)d_in[2];
    const float* b1 = (const float*)d_in[3];
    const float* W2 = (const float*)d_in[4];
    const float* b2 = (const float*)d_in[5];
    float* out = (float*)d_out;

    const int n2 = in_sizes[1];     // 2*E
    const int E  = n2 / 2;

    k_detect<<<1, 256>>>((const int*)ei);
    k_deg_init<<<(NN + 255) / 256, 256>>>();
    k_convert<<<(n2 + 255) / 256, 256>>>(ei, n2, E);
    k_dinv<<<(NN + 255) / 256, 256>>>();
    k_gemm1<<<(NN + 31) / 32, 256>>>(x, W1);
    {
        long long t = (long long)E * 16;
        k_scatter1<<<(unsigned)((t + 255) / 256), 256>>>(E);
    }
    k_gemm2<<<(NN + 255) / 256, 256>>>(b1, W2);
    k_scatter2<<<(E + 255) / 256, 256>>>(E);
    k_final<<<(NN + 255) / 256, 256>>>(out, b2);
}